// round 16
// baseline (speedup 1.0000x reference)
#include <cuda_runtime.h>
#include <cuda_bf16.h>
#include <math.h>
#include <stdint.h>

#define N_NODES 100000
#define N_EDGES 400000
#define N_GRAPHS 2500
#define DIM 128
#define F_IN 78
#define BN_EPS 1e-5f

// ---------------- scratch (device globals; no allocation) ----------------
__device__ float g_t0[N_NODES * DIM];   // branch A temp
__device__ float g_t1[N_NODES * DIM];   // branch B temp
__device__ float g_t2[N_NODES * DIM];   // branch B temp 2
__device__ float g_g1[N_NODES * DIM];
__device__ float g_g2[N_NODES * DIM];
__device__ float g_z1[N_NODES * DIM];   // raw relu(gin) outputs, pre-BN-affine
__device__ float g_z2[N_NODES * DIM];
__device__ float g_z3[N_NODES * DIM];

__device__ int   g_cnt[N_NODES];
__device__ float g_dis[N_NODES];
__device__ int   g_rowptr[N_NODES + 1];
__device__ int   g_cursor[N_NODES];
__device__ int   g_csrc[N_EDGES];
__device__ int   g_blksums[256];
__device__ float g_sum[3 * DIM], g_sumsq[3 * DIM];
__device__ int   g_gstart[N_GRAPHS + 1];

// ---------------- f32x2 packed helpers ----------------
__device__ __forceinline__ unsigned long long pack2(float lo, float hi) {
    unsigned long long r;
    asm("mov.b64 %0, {%1, %2};" : "=l"(r) : "f"(lo), "f"(hi));
    return r;
}
__device__ __forceinline__ void unpack2(unsigned long long v, float& lo, float& hi) {
    asm("mov.b64 {%0, %1}, %2;" : "=f"(lo), "=f"(hi) : "l"(v));
}
__device__ __forceinline__ unsigned long long fma2(unsigned long long a,
                                                   unsigned long long b,
                                                   unsigned long long c) {
    unsigned long long d;
    asm("fma.rn.f32x2 %0, %1, %2, %3;" : "=l"(d) : "l"(a), "l"(b), "l"(c));
    return d;
}

// ---------------- init / CSR build ----------------
__global__ void k_init() {
    int i = blockIdx.x * blockDim.x + threadIdx.x;
    if (i < N_NODES) g_cnt[i] = 0;
    if (i < 3 * DIM) { g_sum[i] = 0.f; g_sumsq[i] = 0.f; }
}

__global__ void k_hist(const int* __restrict__ dst) {
    int e = blockIdx.x * blockDim.x + threadIdx.x;
    if (e < N_EDGES) atomicAdd(&g_cnt[dst[e]], 1);
}

__global__ void k_dis() {
    int i = blockIdx.x * blockDim.x + threadIdx.x;
    if (i < N_NODES) g_dis[i] = rsqrtf((float)(g_cnt[i] + 1));
}

__global__ void k_scan1() {
    __shared__ int s[1024];
    int tid = threadIdx.x;
    int i = blockIdx.x * 1024 + tid;
    int v = (i < N_NODES) ? g_cnt[i] : 0;
    s[tid] = v;
    __syncthreads();
    for (int off = 1; off < 1024; off <<= 1) {
        int t = (tid >= off) ? s[tid - off] : 0;
        __syncthreads();
        s[tid] += t;
        __syncthreads();
    }
    if (i < N_NODES) g_cursor[i] = s[tid];
    if (tid == 1023) g_blksums[blockIdx.x] = s[1023];
}

__global__ void k_scan2(int nblocks) {
    if (threadIdx.x == 0 && blockIdx.x == 0) {
        int run = 0;
        for (int b = 0; b < nblocks; b++) {
            int t = g_blksums[b];
            g_blksums[b] = run;
            run += t;
        }
    }
}

__global__ void k_scan3() {
    int i = blockIdx.x * blockDim.x + threadIdx.x;
    if (i < N_NODES) {
        int val = g_cursor[i] + g_blksums[i >> 10];
        g_rowptr[i + 1] = val;
        g_cursor[i] = val - g_cnt[i];
        if (i == 0) g_rowptr[0] = 0;
    }
}

__global__ void k_scatter(const int* __restrict__ src, const int* __restrict__ dst) {
    int e = blockIdx.x * blockDim.x + threadIdx.x;
    if (e < N_EDGES) {
        int d = dst[e];
        int pos = atomicAdd(&g_cursor[d], 1);
        g_csrc[pos] = src[e];
    }
}

__global__ void k_gstart(const int* __restrict__ batch) {
    int g = blockIdx.x * blockDim.x + threadIdx.x;
    if (g <= N_GRAPHS) {
        int lo = 0, hi = N_NODES;
        while (lo < hi) {
            int mid = (lo + hi) >> 1;
            if (batch[mid] < g) lo = mid + 1; else hi = mid;
        }
        g_gstart[g] = lo;
    }
}

// ---------------- GEMM: C[100000 x 128] = A[. x K] @ W[K x 128] ----------------
// 128x128 tile, 256 threads, 8x8 per thread via packed f32x2 FMA.
// A tile stored PRE-DUPLICATED in smem as u64 {a,a} -> mainloop needs no pack2.
#define TM 128
#define KC 32
#define A2ST (TM + 2)   // u64 row stride (130*8 = 1040B)
// dynamic smem layout (bytes): As2 u64[KC][A2ST] | Bs f32[KC][DIM] | Sred f32[16][DIM]
#define B_AS2 0
#define B_BS (B_AS2 + KC * A2ST * 8)
#define B_SR (B_BS + KC * DIM * 4)
#define SMEM_GEMM_BYTES (B_SR + 16 * DIM * 4)

template <int K, bool BIAS, bool RELU, int STATS>
__global__ void __launch_bounds__(256) k_gemm(const float* __restrict__ A,
                                              const float* __restrict__ W,
                                              const float* __restrict__ bias,
                                              float* __restrict__ C) {
    extern __shared__ char smraw[];
    unsigned long long (*As2)[A2ST] = (unsigned long long(*)[A2ST])(smraw + B_AS2);
    float (*Bs)[DIM] = (float(*)[DIM])(smraw + B_BS);
    float (*Sred)[DIM] = (float(*)[DIM])(smraw + B_SR);

    const int tid = threadIdx.x;
    const int tx = tid & 15;   // 8 cols: tx*8 .. tx*8+7
    const int ty = tid >> 4;   // 8 rows: ty*4..+3 and 64+ty*4..+3
    const int row0 = blockIdx.x * TM;

    unsigned long long acc[8][4];
#pragma unroll
    for (int i = 0; i < 8; i++)
#pragma unroll
        for (int j = 0; j < 4; j++) acc[i][j] = 0ull;

    constexpr int KSTEPS = (K + KC - 1) / KC;
    for (int s = 0; s < KSTEPS; s++) {
        const int kk = s * KC;
        // --- load A tile (TM x KC), transposed + duplicated into As2[k][m] = {a,a} ---
        if constexpr (K % KC == 0) {
#pragma unroll
            for (int t = 0; t < 4; t++) {
                int idx = tid + t * 256;       // 1024 float4
                int r = idx >> 3, c4 = idx & 7;
                float4 v = make_float4(0.f, 0.f, 0.f, 0.f);
                int grow = row0 + r;
                if (grow < N_NODES) v = *(const float4*)&A[grow * K + kk + c4 * 4];
                As2[c4 * 4 + 0][r] = pack2(v.x, v.x);
                As2[c4 * 4 + 1][r] = pack2(v.y, v.y);
                As2[c4 * 4 + 2][r] = pack2(v.z, v.z);
                As2[c4 * 4 + 3][r] = pack2(v.w, v.w);
            }
        } else {
#pragma unroll
            for (int t = 0; t < 16; t++) {
                int idx = tid + t * 256;       // 4096 scalars
                int r = idx >> 5, c = idx & 31;
                int grow = row0 + r, gcol = kk + c;
                float v = 0.f;
                if (grow < N_NODES && gcol < K) v = A[grow * K + gcol];
                As2[c][r] = pack2(v, v);
            }
        }
        // --- load B tile (KC x 128) ---
#pragma unroll
        for (int t = 0; t < 4; t++) {
            int idx = tid + t * 256;           // 1024 float4
            int k = idx >> 5, c4 = idx & 31;
            int gk = kk + k;
            float4 v = make_float4(0.f, 0.f, 0.f, 0.f);
            if (gk < K) v = *(const float4*)&W[gk * DIM + c4 * 4];
            *(float4*)&Bs[k][c4 * 4] = v;
        }
        __syncthreads();

#pragma unroll 8
        for (int k = 0; k < KC; k++) {
            ulonglong2 aq0 = *(const ulonglong2*)&As2[k][ty * 4];
            ulonglong2 aq1 = *(const ulonglong2*)&As2[k][ty * 4 + 2];
            ulonglong2 aq2 = *(const ulonglong2*)&As2[k][64 + ty * 4];
            ulonglong2 aq3 = *(const ulonglong2*)&As2[k][64 + ty * 4 + 2];
            ulonglong2 bq0 = *(const ulonglong2*)&Bs[k][tx * 8];
            ulonglong2 bq1 = *(const ulonglong2*)&Bs[k][tx * 8 + 4];
            unsigned long long B[4] = {bq0.x, bq0.y, bq1.x, bq1.y};
            unsigned long long Ap[8] = {aq0.x, aq0.y, aq1.x, aq1.y,
                                        aq2.x, aq2.y, aq3.x, aq3.y};
#pragma unroll
            for (int i = 0; i < 8; i++)
#pragma unroll
                for (int j = 0; j < 4; j++)
                    acc[i][j] = fma2(Ap[i], B[j], acc[i][j]);
        }
        __syncthreads();
    }

    float bv[8];
#pragma unroll
    for (int j = 0; j < 8; j++) bv[j] = BIAS ? bias[tx * 8 + j] : 0.f;

    float cs[8], cq[8];
#pragma unroll
    for (int j = 0; j < 8; j++) { cs[j] = 0.f; cq[j] = 0.f; }

#pragma unroll
    for (int i = 0; i < 8; i++) {
        int row = row0 + ((i < 4) ? (ty * 4 + i) : (64 + ty * 4 + i - 4));
        float v[8];
#pragma unroll
        for (int j = 0; j < 4; j++) unpack2(acc[i][j], v[2 * j], v[2 * j + 1]);
#pragma unroll
        for (int j = 0; j < 8; j++) {
            v[j] += bv[j];
            if (RELU) v[j] = fmaxf(v[j], 0.f);
        }
        if (row < N_NODES) {
            *(float4*)&C[row * DIM + tx * 8] = make_float4(v[0], v[1], v[2], v[3]);
            *(float4*)&C[row * DIM + tx * 8 + 4] = make_float4(v[4], v[5], v[6], v[7]);
            if (STATS >= 0) {
#pragma unroll
                for (int j = 0; j < 8; j++) { cs[j] += v[j]; cq[j] += v[j] * v[j]; }
            }
        }
    }

    if constexpr (STATS >= 0) {
#pragma unroll
        for (int j = 0; j < 8; j++) Sred[ty][tx * 8 + j] = cs[j];
        __syncthreads();
        if (tid < DIM) {
            float t = 0.f;
#pragma unroll
            for (int r = 0; r < 16; r++) t += Sred[r][tid];
            atomicAdd(&g_sum[STATS * DIM + tid], t);
        }
        __syncthreads();
#pragma unroll
        for (int j = 0; j < 8; j++) Sred[ty][tx * 8 + j] = cq[j];
        __syncthreads();
        if (tid < DIM) {
            float t = 0.f;
#pragma unroll
            for (int r = 0; r < 16; r++) t += Sred[r][tid];
            atomicAdd(&g_sumsq[STATS * DIM + tid], t);
        }
    }
}

// ---------------- inline BN affine from stats ----------------
__device__ __forceinline__ void bn_affine4(int layer, int c0,
                                           const float* __restrict__ gamma,
                                           const float* __restrict__ beta,
                                           float4& a, float4& b) {
    float4 s = *(const float4*)&g_sum[layer * DIM + c0];
    float4 q = *(const float4*)&g_sumsq[layer * DIM + c0];
    float4 gm = *(const float4*)&gamma[c0];
    float4 bt = *(const float4*)&beta[c0];
    const float inv = 1.f / N_NODES;
    float mu, var;
    mu = s.x * inv; var = q.x * inv - mu * mu; a.x = rsqrtf(var + BN_EPS) * gm.x; b.x = bt.x - mu * a.x;
    mu = s.y * inv; var = q.y * inv - mu * mu; a.y = rsqrtf(var + BN_EPS) * gm.y; b.y = bt.y - mu * a.y;
    mu = s.z * inv; var = q.z * inv - mu * mu; a.z = rsqrtf(var + BN_EPS) * gm.z; b.z = bt.z - mu * a.z;
    mu = s.w * inv; var = q.w * inv - mu * mu; a.w = rsqrtf(var + BN_EPS) * gm.w; b.w = bt.w - mu * a.w;
}

// ---------------- GCN aggregation ----------------
__global__ void k_gcn_agg(const float* __restrict__ h, const float* __restrict__ bias,
                          float* __restrict__ out) {
    int gt = blockIdx.x * blockDim.x + threadIdx.x;
    int node = gt >> 5;
    int lane = gt & 31;
    if (node >= N_NODES) return;
    float dn = g_dis[node];
    float4 acc = *(const float4*)&h[node * DIM + lane * 4];
    acc.x *= dn; acc.y *= dn; acc.z *= dn; acc.w *= dn;
    int e0 = g_rowptr[node], e1 = g_rowptr[node + 1];
    for (int e = e0; e < e1; e++) {
        int s = g_csrc[e];
        float ds = g_dis[s];
        float4 v = *(const float4*)&h[s * DIM + lane * 4];
        acc.x += v.x * ds; acc.y += v.y * ds;
        acc.z += v.z * ds; acc.w += v.w * ds;
    }
    float4 b = *(const float4*)&bias[lane * 4];
    float4 r;
    r.x = fmaxf(acc.x * dn + b.x, 0.f);
    r.y = fmaxf(acc.y * dn + b.y, 0.f);
    r.z = fmaxf(acc.z * dn + b.z, 0.f);
    r.w = fmaxf(acc.w * dn + b.w, 0.f);
    *(float4*)&out[node * DIM + lane * 4] = r;
}

// ---------------- GIN aggregation with inline-computed BN affine ----------------
// out = a[c]*(z_i + sum z_s) + b[c]*(deg+1)
__global__ void k_gin_agg_affine(const float* __restrict__ z, int layer,
                                 const float* __restrict__ gamma,
                                 const float* __restrict__ beta,
                                 float* __restrict__ out) {
    int gt = blockIdx.x * blockDim.x + threadIdx.x;
    int node = gt >> 5;
    int lane = gt & 31;
    if (node >= N_NODES) return;
    float4 a, b;
    bn_affine4(layer, lane * 4, gamma, beta, a, b);
    float4 acc = *(const float4*)&z[node * DIM + lane * 4];
    int e0 = g_rowptr[node], e1 = g_rowptr[node + 1];
    for (int e = e0; e < e1; e++) {
        int s = g_csrc[e];
        float4 v = *(const float4*)&z[s * DIM + lane * 4];
        acc.x += v.x; acc.y += v.y; acc.z += v.z; acc.w += v.w;
    }
    float m = (float)(e1 - e0 + 1);
    float4 r;
    r.x = a.x * acc.x + b.x * m;
    r.y = a.y * acc.y + b.y * m;
    r.z = a.z * acc.z + b.z * m;
    r.w = a.w * acc.w + b.w * m;
    *(float4*)&out[node * DIM + lane * 4] = r;
}

// ---------------- GIN layer-0 aggregation (F_IN=78) ----------------
__global__ void k_gin_agg78(const float* __restrict__ x, float* __restrict__ out) {
    int gt = blockIdx.x * blockDim.x + threadIdx.x;
    int node = gt >> 5;
    int lane = gt & 31;
    if (node >= N_NODES) return;
    bool has2 = (lane + 64) < F_IN;
    float a0 = x[node * F_IN + lane];
    float a1 = x[node * F_IN + lane + 32];
    float a2 = has2 ? x[node * F_IN + lane + 64] : 0.f;
    int e0 = g_rowptr[node], e1 = g_rowptr[node + 1];
    for (int e = e0; e < e1; e++) {
        int s = g_csrc[e];
        a0 += x[s * F_IN + lane];
        a1 += x[s * F_IN + lane + 32];
        if (has2) a2 += x[s * F_IN + lane + 64];
    }
    out[node * F_IN + lane] = a0;
    out[node * F_IN + lane + 32] = a1;
    if (has2) out[node * F_IN + lane + 64] = a2;
}

// ---------------- readout (computes BN affine inline) ----------------
__global__ void k_readout(const float* __restrict__ gamma, const float* __restrict__ beta,
                          float* __restrict__ out) {
    int g = blockIdx.x;
    int c = threadIdx.x;  // 128
    int r0 = g_gstart[g], r1 = g_gstart[g + 1];
    const float inv = 1.f / N_NODES;
    float ac[3], bc[3];
#pragma unroll
    for (int l = 0; l < 3; l++) {
        float mu = g_sum[l * DIM + c] * inv;
        float var = g_sumsq[l * DIM + c] * inv - mu * mu;
        ac[l] = rsqrtf(var + BN_EPS) * gamma[l * DIM + c];
        bc[l] = beta[l * DIM + c] - mu * ac[l];
    }
    float m1 = -INFINITY, m2 = -INFINITY, m3 = -INFINITY;
    float m4 = -INFINITY, m5 = -INFINITY, m6 = -INFINITY;
    float m7 = -INFINITY, m8 = -INFINITY, m9 = -INFINITY;
    for (int r = r0; r < r1; r++) {
        float a = fmaf(ac[0], g_z1[r * DIM + c], bc[0]);
        float b = fmaf(ac[1], g_z2[r * DIM + c], bc[1]);
        float d = fmaf(ac[2], g_z3[r * DIM + c], bc[2]);
        float e1 = g_g1[r * DIM + c];
        float e2 = g_g2[r * DIM + c];
        m1 = fmaxf(m1, a); m2 = fmaxf(m2, b); m3 = fmaxf(m3, d);
        m4 = fmaxf(m4, a * b * d);
        m5 = fmaxf(m5, a + b + d);
        m6 = fmaxf(m6, e1); m7 = fmaxf(m7, e2);
        m8 = fmaxf(m8, e2 + e1); m9 = fmaxf(m9, e2 * e1);
    }
    float* o = out + (size_t)g * (9 * DIM);
    o[0 * DIM + c] = m1; o[1 * DIM + c] = m2; o[2 * DIM + c] = m3;
    o[3 * DIM + c] = m4; o[4 * DIM + c] = m5; o[5 * DIM + c] = m6;
    o[6 * DIM + c] = m7; o[7 * DIM + c] = m8; o[8 * DIM + c] = m9;
}

// ---------------- launch ----------------
extern "C" void kernel_launch(void* const* d_in, const int* in_sizes, int n_in,
                              void* d_out, int out_size) {
    const float* x = (const float*)d_in[0];
    const int* ei = (const int*)d_in[1];
    const int* src = ei;
    const int* dst = ei + N_EDGES;
    const int* batch = (const int*)d_in[2];
    int base = (n_in >= 18) ? 4 : 3;
    const float* gcn1_W = (const float*)d_in[base + 0];
    const float* gcn1_b = (const float*)d_in[base + 1];
    const float* gcn2_W = (const float*)d_in[base + 2];
    const float* gcn2_b = (const float*)d_in[base + 3];
    const float* gin0_w1 = (const float*)d_in[base + 4];
    const float* gin0_b1 = (const float*)d_in[base + 5];
    const float* gin0_w2 = (const float*)d_in[base + 6];
    const float* gin0_b2 = (const float*)d_in[base + 7];
    const float* gin_w1 = (const float*)d_in[base + 8];
    const float* gin_b1 = (const float*)d_in[base + 9];
    const float* gin_w2 = (const float*)d_in[base + 10];
    const float* gin_b2 = (const float*)d_in[base + 11];
    const float* bn_gamma = (const float*)d_in[base + 12];
    const float* bn_beta = (const float*)d_in[base + 13];
    float* out = (float*)d_out;

    float *t0 = nullptr, *t1 = nullptr, *t2 = nullptr;
    float *g1 = nullptr, *g2 = nullptr;
    float *z1 = nullptr, *z2 = nullptr, *z3 = nullptr;
    cudaGetSymbolAddress((void**)&t0, g_t0);
    cudaGetSymbolAddress((void**)&t1, g_t1);
    cudaGetSymbolAddress((void**)&t2, g_t2);
    cudaGetSymbolAddress((void**)&g1, g_g1);
    cudaGetSymbolAddress((void**)&g2, g_g2);
    cudaGetSymbolAddress((void**)&z1, g_z1);
    cudaGetSymbolAddress((void**)&z2, g_z2);
    cudaGetSymbolAddress((void**)&z3, g_z3);

    static cudaStream_t sA = nullptr, sB = nullptr;
    static cudaEvent_t evStart = nullptr, evCSR = nullptr, evA = nullptr, evB = nullptr;
    if (!sA) {
        cudaStreamCreateWithFlags(&sA, cudaStreamNonBlocking);
        cudaStreamCreateWithFlags(&sB, cudaStreamNonBlocking);
        cudaEventCreateWithFlags(&evStart, cudaEventDisableTiming);
        cudaEventCreateWithFlags(&evCSR, cudaEventDisableTiming);
        cudaEventCreateWithFlags(&evA, cudaEventDisableTiming);
        cudaEventCreateWithFlags(&evB, cudaEventDisableTiming);
        cudaFuncSetAttribute(k_gemm<F_IN, false, false, -1>, cudaFuncAttributeMaxDynamicSharedMemorySize, SMEM_GEMM_BYTES);
        cudaFuncSetAttribute(k_gemm<DIM, false, false, -1>, cudaFuncAttributeMaxDynamicSharedMemorySize, SMEM_GEMM_BYTES);
        cudaFuncSetAttribute(k_gemm<F_IN, true, true, -1>, cudaFuncAttributeMaxDynamicSharedMemorySize, SMEM_GEMM_BYTES);
        cudaFuncSetAttribute(k_gemm<DIM, true, true, -1>, cudaFuncAttributeMaxDynamicSharedMemorySize, SMEM_GEMM_BYTES);
        cudaFuncSetAttribute(k_gemm<DIM, true, true, 0>, cudaFuncAttributeMaxDynamicSharedMemorySize, SMEM_GEMM_BYTES);
        cudaFuncSetAttribute(k_gemm<DIM, true, true, 1>, cudaFuncAttributeMaxDynamicSharedMemorySize, SMEM_GEMM_BYTES);
        cudaFuncSetAttribute(k_gemm<DIM, true, true, 2>, cudaFuncAttributeMaxDynamicSharedMemorySize, SMEM_GEMM_BYTES);
    }

    const int NB_N = (N_NODES + 255) / 256;
    const int NB_E = (N_EDGES + 255) / 256;
    const int NB_GEMM = (N_NODES + TM - 1) / TM;
    const int NB_AGG = (N_NODES * 32 + 255) / 256;
    const int SCAN_BLOCKS = (N_NODES + 1023) / 1024;

    // ---- fork ----
    cudaEventRecord(evStart, 0);
    cudaStreamWaitEvent(sA, evStart, 0);
    cudaStreamWaitEvent(sB, evStart, 0);

    // ---- stream 0: CSR build ----
    k_init<<<NB_N, 256>>>();
    k_hist<<<NB_E, 256>>>(dst);
    k_dis<<<NB_N, 256>>>();
    k_scan1<<<SCAN_BLOCKS, 1024>>>();
    k_scan2<<<1, 1>>>(SCAN_BLOCKS);
    k_scan3<<<NB_N, 256>>>();
    k_scatter<<<NB_E, 256>>>(src, dst);
    cudaEventRecord(evCSR, 0);
    k_gstart<<<(N_GRAPHS + 1 + 255) / 256, 256>>>(batch);

    // ---- branch A (sA): GCN chain ----
    k_gemm<F_IN, false, false, -1><<<NB_GEMM, 256, SMEM_GEMM_BYTES, sA>>>(x, gcn1_W, nullptr, t0);
    cudaStreamWaitEvent(sA, evCSR, 0);
    k_gcn_agg<<<NB_AGG, 256, 0, sA>>>(t0, gcn1_b, g1);
    k_gemm<DIM, false, false, -1><<<NB_GEMM, 256, SMEM_GEMM_BYTES, sA>>>(g1, gcn2_W, nullptr, t0);
    k_gcn_agg<<<NB_AGG, 256, 0, sA>>>(t0, gcn2_b, g2);
    cudaEventRecord(evA, sA);

    // ---- branch B (sB): GIN chain ----
    cudaStreamWaitEvent(sB, evCSR, 0);
    k_gin_agg78<<<NB_AGG, 256, 0, sB>>>(x, t1);
    k_gemm<F_IN, true, true, -1><<<NB_GEMM, 256, SMEM_GEMM_BYTES, sB>>>(t1, gin0_w1, gin0_b1, t2);
    k_gemm<DIM, true, true, 0><<<NB_GEMM, 256, SMEM_GEMM_BYTES, sB>>>(t2, gin0_w2, gin0_b2, z1);

    k_gin_agg_affine<<<NB_AGG, 256, 0, sB>>>(z1, 0, bn_gamma + 0 * DIM, bn_beta + 0 * DIM, t1);
    k_gemm<DIM, true, true, -1><<<NB_GEMM, 256, SMEM_GEMM_BYTES, sB>>>(t1, gin_w1 + 0 * DIM * DIM, gin_b1 + 0 * DIM, t2);
    k_gemm<DIM, true, true, 1><<<NB_GEMM, 256, SMEM_GEMM_BYTES, sB>>>(t2, gin_w2 + 0 * DIM * DIM, gin_b2 + 0 * DIM, z2);

    k_gin_agg_affine<<<NB_AGG, 256, 0, sB>>>(z2, 1, bn_gamma + 1 * DIM, bn_beta + 1 * DIM, t1);
    k_gemm<DIM, true, true, -1><<<NB_GEMM, 256, SMEM_GEMM_BYTES, sB>>>(t1, gin_w1 + 1 * DIM * DIM, gin_b1 + 1 * DIM, t2);
    k_gemm<DIM, true, true, 2><<<NB_GEMM, 256, SMEM_GEMM_BYTES, sB>>>(t2, gin_w2 + 1 * DIM * DIM, gin_b2 + 1 * DIM, z3);
    cudaEventRecord(evB, sB);

    // ---- join + readout ----
    cudaStreamWaitEvent(0, evA, 0);
    cudaStreamWaitEvent(0, evB, 0);
    k_readout<<<N_GRAPHS, 128>>>(bn_gamma, bn_beta, out);
}